// round 8
// baseline (speedup 1.0000x reference)
#include <cuda_runtime.h>
#include <cuda_bf16.h>
#include <math.h>
#include <stdint.h>

typedef __nv_bfloat16 bf16;

#define BB    8
#define NTOK  16384
#define CC    64
#define HIDD  256
#define NRTOK 256
#define MTOT  (BB*NTOK)   // 131072

// ---------------- scratch ----------------
__device__ bf16  g_hb [(size_t)MTOT*CC];
__device__ bf16  g_qb [(size_t)MTOT*CC];
__device__ float g_x2 [(size_t)MTOT*CC];
__device__ bf16  g_fb [(size_t)MTOT*HIDD];
__device__ bf16  g_kvb[(size_t)2048*2*CC];
__device__ bf16  g_wq [64*64];
__device__ bf16  g_wkv[64*128];
__device__ bf16  g_wp [64*64];
__device__ bf16  g_wsr[4096*64];
__device__ bf16  g_w1 [64*256];
__device__ bf16  g_w2 [256*64];

// ---------------- helpers ----------------
__device__ __forceinline__ void mma_bf16(float& d0,float& d1,float& d2,float& d3,
    uint32_t a0,uint32_t a1,uint32_t a2,uint32_t a3,uint32_t b0,uint32_t b1){
  asm volatile("mma.sync.aligned.m16n8k16.row.col.f32.bf16.bf16.f32 "
    "{%0,%1,%2,%3}, {%4,%5,%6,%7}, {%8,%9}, {%0,%1,%2,%3};\n"
    : "+f"(d0),"+f"(d1),"+f"(d2),"+f"(d3)
    : "r"(a0),"r"(a1),"r"(a2),"r"(a3),"r"(b0),"r"(b1));
}
__device__ __forceinline__ void ldsm_x4(uint32_t* r, uint32_t addr){
  asm volatile("ldmatrix.sync.aligned.m8n8.x4.shared.b16 {%0,%1,%2,%3}, [%4];\n"
    : "=r"(r[0]),"=r"(r[1]),"=r"(r[2]),"=r"(r[3]) : "r"(addr));
}
__device__ __forceinline__ void ldsm_x4_t(uint32_t* r, uint32_t addr){
  asm volatile("ldmatrix.sync.aligned.m8n8.x4.trans.shared.b16 {%0,%1,%2,%3}, [%4];\n"
    : "=r"(r[0]),"=r"(r[1]),"=r"(r[2]),"=r"(r[3]) : "r"(addr));
}
__device__ __forceinline__ uint32_t pack2(float lo, float hi){
  __nv_bfloat162 v = __floats2bfloat162_rn(lo, hi);
  return reinterpret_cast<uint32_t&>(v);
}
__device__ __forceinline__ void cp_async16(uint32_t saddr, const void* gptr){
  asm volatile("cp.async.ca.shared.global [%0], [%1], 16;\n" :: "r"(saddr), "l"(gptr));
}
__device__ __forceinline__ void cp_async_commit(){ asm volatile("cp.async.commit_group;\n"); }
__device__ __forceinline__ void cp_async_wait0(){ asm volatile("cp.async.wait_group 0;\n"); }
__device__ __forceinline__ void cp_async_wait1(){ asm volatile("cp.async.wait_group 1;\n"); }

// ---------------- weight conversions ----------------
struct CvtArgs {
  const float* s0; const float* s1; const float* s2;
  const float* s3; const float* s4; const float* s5;
  bf16 *d0,*d1,*d2,*d3,*d4,*d5;
};
__global__ void __launch_bounds__(256) cvt_all(CvtArgs a){
  int i = blockIdx.x*256 + threadIdx.x;
  if (i < 4096)                { a.d0[i] = __float2bfloat16(a.s0[i]); return; }
  if (i < 12288)               { int j=i-4096;   a.d1[j] = __float2bfloat16(a.s1[j]); return; }
  if (i < 16384)               { int j=i-12288;  a.d2[j] = __float2bfloat16(a.s2[j]); return; }
  if (i < 278528)              { int j=i-16384;  a.d3[j] = __float2bfloat16(a.s3[j]); return; }
  if (i < 294912)              { int j=i-278528; a.d4[j] = __float2bfloat16(a.s4[j]); return; }
  if (i < 311296)              { int j=i-294912; a.d5[j] = __float2bfloat16(a.s5[j]); return; }
}

// ---------------- fused LN1 + q-GEMM ----------------
__global__ void __launch_bounds__(256) ln1q_kernel(
    const float* __restrict__ x, const bf16* __restrict__ wq,
    const float* __restrict__ qbias, const float* __restrict__ g1,
    const float* __restrict__ b1, bf16* __restrict__ hb, bf16* __restrict__ qb)
{
  __shared__ bf16 Ws[64*72];
  __shared__ bf16 As[128*72];
  int t = threadIdx.x, w = t>>5, lane = t&31;
  size_t rowbase = (size_t)blockIdx.x * 128;

  for (int i = t; i < 512; i += 256){
    int row = i>>3, c8 = i&7;
    *(float4*)(Ws + row*72 + c8*8) = *(const float4*)(wq + row*64 + c8*8);
  }
  {
    int r = t>>1, half = t&1, col0 = half*32;
    const float* xr = x + (rowbase + r)*64 + col0;
    float v[32];
    #pragma unroll
    for (int j = 0; j < 8; j++) *(float4*)(v + j*4) = *(const float4*)(xr + j*4);
    float s = 0.f;
    #pragma unroll
    for (int j = 0; j < 32; j++) s += v[j];
    s += __shfl_xor_sync(0xffffffffu, s, 1);
    float mean = s * (1.0f/64.0f);
    float qv = 0.f;
    #pragma unroll
    for (int j = 0; j < 32; j++){ float d = v[j]-mean; qv += d*d; }
    qv += __shfl_xor_sync(0xffffffffu, qv, 1);
    float rstd = rsqrtf(qv*(1.0f/64.0f) + 1e-5f);
    #pragma unroll
    for (int j = 0; j < 16; j++){
      int c = col0 + 2*j;
      float2 gg = *(const float2*)(g1 + c);
      float2 bb = *(const float2*)(b1 + c);
      uint32_t u = pack2((v[2*j]-mean)*rstd*gg.x + bb.x,
                         (v[2*j+1]-mean)*rstd*gg.y + bb.y);
      *(uint32_t*)(As + r*72 + c) = u;
      *(uint32_t*)(hb + (rowbase + r)*64 + c) = u;
    }
  }
  __syncthreads();

  float acc[8][4];
  #pragma unroll
  for (int nb = 0; nb < 8; nb++){ acc[nb][0]=acc[nb][1]=acc[nb][2]=acc[nb][3]=0.f; }
  uint32_t As_u = (uint32_t)__cvta_generic_to_shared(As);
  uint32_t Ws_u = (uint32_t)__cvta_generic_to_shared(Ws);
  uint32_t a_base = As_u + ((w*16 + (lane&15))*72 + (lane>>4)*8)*2;
  uint32_t b_off  = (lane&15)*144 + (lane>>4)*16;
  #pragma unroll
  for (int kb = 0; kb < 4; kb++){
    uint32_t a[4];
    ldsm_x4(a, a_base + kb*32);
    uint32_t brow = Ws_u + (uint32_t)(kb*16)*144 + b_off;
    #pragma unroll
    for (int n2 = 0; n2 < 4; n2++){
      uint32_t b[4];
      ldsm_x4_t(b, brow + n2*32);
      mma_bf16(acc[2*n2  ][0],acc[2*n2  ][1],acc[2*n2  ][2],acc[2*n2  ][3],
               a[0],a[1],a[2],a[3], b[0],b[1]);
      mma_bf16(acc[2*n2+1][0],acc[2*n2+1][1],acc[2*n2+1][2],acc[2*n2+1][3],
               a[0],a[1],a[2],a[3], b[2],b[3]);
    }
  }
  int g = lane>>2, tq = lane&3;
  size_t r0 = rowbase + w*16 + g, r1 = r0 + 8;
  #pragma unroll
  for (int nb = 0; nb < 8; nb++){
    int col = nb*8 + tq*2;
    float b0 = qbias[col], b1v = qbias[col+1];
    *(uint32_t*)(qb + r0*64 + col) = pack2((acc[nb][0]+b0)*0.125f, (acc[nb][1]+b1v)*0.125f);
    *(uint32_t*)(qb + r1*64 + col) = pack2((acc[nb][2]+b0)*0.125f, (acc[nb][3]+b1v)*0.125f);
  }
}

// ---- fused sr-conv (full K, cp.async double buffered) + srn-LN + kv GEMM ----
// smem layout (bf16 elems):
//  Wkv  [0, 8704)        64 x 136
//  A0   [8704, 13312)    64 x 72
//  A1   [13312, 17920)
//  W0   [17920, 22528)   64 x 72
//  W1   [22528, 27136)
//  Cs   floats at byte 54272, 64 x 68
#define SKV_SMEM (54272 + 64*68*4)
__global__ void __launch_bounds__(256) spatial_kv(
    const bf16* __restrict__ h, const bf16* __restrict__ wsr,
    const float* __restrict__ srb, const float* __restrict__ gamma,
    const float* __restrict__ beta, const bf16* __restrict__ wkv,
    const float* __restrict__ kvbias, bf16* __restrict__ kvout)
{
  extern __shared__ bf16 smk[];
  bf16* Wkv = smk;
  bf16* Ab[2] = { smk + 8704, smk + 13312 };
  bf16* Wb[2] = { smk + 17920, smk + 22528 };
  float* Cs = (float*)((char*)smk + 54272);
  int t = threadIdx.x, w = t>>5, lane = t&31;
  int pbase = blockIdx.x * 64;
  uint32_t base_u = (uint32_t)__cvta_generic_to_shared(smk);

  for (int i = t; i < 1024; i += 256){
    int row = i>>4, c8 = i&15;
    *(float4*)(Wkv + row*136 + c8*8) = *(const float4*)(wkv + row*128 + c8*8);
  }

  // stage chunk kk into buffer s
  auto stage = [&](int kk, int s){
    int r1 = kk>>3, c2 = kk&7;
    #pragma unroll
    for (int i = t; i < 512; i += 256){
      int pl = i>>3, c8 = i&7;
      int p = pbase + pl;
      int b = p>>8, ph = (p>>4)&15, pw = p&15;
      const bf16* src = h + (((size_t)b*128 + ph*8 + r1)*128 + pw*8 + c2)*64 + c8*8;
      cp_async16(base_u + (uint32_t)((8704 + s*4608) + pl*72 + c8*8)*2, src);
    }
    #pragma unroll
    for (int i = t; i < 512; i += 256){
      int row = i>>3, c8 = i&7;
      const bf16* src = wsr + ((size_t)kk*64 + row)*64 + c8*8;
      cp_async16(base_u + (uint32_t)((17920 + s*4608) + row*72 + c8*8)*2, src);
    }
    cp_async_commit();
  };

  // conv accum: warp w -> rows (w&3)*16.., cols (w>>2)*32..
  float acc[4][4];
  #pragma unroll
  for (int nb = 0; nb < 4; nb++){ acc[nb][0]=acc[nb][1]=acc[nb][2]=acc[nb][3]=0.f; }
  uint32_t a_off = (((w&3)*16 + (lane&15))*72 + (lane>>4)*8)*2;
  uint32_t b_off = (lane&15)*144 + (lane>>4)*16 + (w>>2)*64;

  stage(0, 0);
  for (int kk = 0; kk < 64; kk++){
    int cur = kk & 1;
    if (kk < 63) stage(kk+1, 1-cur);
    if (kk < 63) cp_async_wait1(); else cp_async_wait0();
    __syncthreads();
    uint32_t Abase = base_u + (uint32_t)(8704 + cur*4608)*2;
    uint32_t Wbase = base_u + (uint32_t)(17920 + cur*4608)*2;
    #pragma unroll
    for (int kb = 0; kb < 4; kb++){
      uint32_t a[4];
      ldsm_x4(a, Abase + a_off + kb*32);
      uint32_t brow = Wbase + (uint32_t)(kb*16)*144 + b_off;
      #pragma unroll
      for (int n2 = 0; n2 < 2; n2++){
        uint32_t b[4];
        ldsm_x4_t(b, brow + n2*32);
        mma_bf16(acc[2*n2  ][0],acc[2*n2  ][1],acc[2*n2  ][2],acc[2*n2  ][3],
                 a[0],a[1],a[2],a[3], b[0],b[1]);
        mma_bf16(acc[2*n2+1][0],acc[2*n2+1][1],acc[2*n2+1][2],acc[2*n2+1][3],
                 a[0],a[1],a[2],a[3], b[2],b[3]);
      }
    }
    __syncthreads();
  }

  // write conv result to Cs
  {
    int g = lane>>2, tq = lane&3;
    int row0 = (w&3)*16 + g;
    #pragma unroll
    for (int nb = 0; nb < 4; nb++){
      int col = (w>>2)*32 + nb*8 + tq*2;
      *(float2*)(Cs + row0*68 + col)     = make_float2(acc[nb][0], acc[nb][1]);
      *(float2*)(Cs + (row0+8)*68 + col) = make_float2(acc[nb][2], acc[nb][3]);
    }
  }
  __syncthreads();

  // LN (+srb) -> As (reuse A0)
  bf16* As = Ab[0];
  if (t < 128){
    int r = t>>1, half = t&1, col0 = half*32;
    float v[32];
    #pragma unroll
    for (int j = 0; j < 32; j++) v[j] = Cs[r*68 + col0 + j] + srb[col0 + j];
    float s = 0.f;
    #pragma unroll
    for (int j = 0; j < 32; j++) s += v[j];
    s += __shfl_xor_sync(0xffffffffu, s, 1);
    float mean = s * (1.0f/64.0f);
    float qv = 0.f;
    #pragma unroll
    for (int j = 0; j < 32; j++){ float d = v[j]-mean; qv += d*d; }
    qv += __shfl_xor_sync(0xffffffffu, qv, 1);
    float rstd = rsqrtf(qv*(1.0f/64.0f) + 1e-5f);
    #pragma unroll
    for (int j = 0; j < 16; j++){
      int c = col0 + 2*j;
      float2 gg = *(const float2*)(gamma + c);
      float2 bb = *(const float2*)(beta + c);
      *(uint32_t*)(As + r*72 + c) = pack2((v[2*j]-mean)*rstd*gg.x + bb.x,
                                          (v[2*j+1]-mean)*rstd*gg.y + bb.y);
    }
  }
  __syncthreads();

  // kv GEMM: warp w -> rows (w&3)*16.., col half (w>>2)*64..
  float kacc[8][4];
  #pragma unroll
  for (int nb = 0; nb < 8; nb++){ kacc[nb][0]=kacc[nb][1]=kacc[nb][2]=kacc[nb][3]=0.f; }
  uint32_t As_u = base_u + 8704*2;
  uint32_t Wk_u = base_u;
  uint32_t a2_base = As_u + (((w&3)*16 + (lane&15))*72 + (lane>>4)*8)*2;
  uint32_t b2_off  = (lane&15)*272 + (lane>>4)*16 + (w>>2)*128;
  #pragma unroll
  for (int kb = 0; kb < 4; kb++){
    uint32_t a[4];
    ldsm_x4(a, a2_base + kb*32);
    uint32_t brow = Wk_u + (uint32_t)(kb*16)*272 + b2_off;
    #pragma unroll
    for (int n2 = 0; n2 < 4; n2++){
      uint32_t b[4];
      ldsm_x4_t(b, brow + n2*32);
      mma_bf16(kacc[2*n2  ][0],kacc[2*n2  ][1],kacc[2*n2  ][2],kacc[2*n2  ][3],
               a[0],a[1],a[2],a[3], b[0],b[1]);
      mma_bf16(kacc[2*n2+1][0],kacc[2*n2+1][1],kacc[2*n2+1][2],kacc[2*n2+1][3],
               a[0],a[1],a[2],a[3], b[2],b[3]);
    }
  }
  int g = lane>>2, tq = lane&3;
  size_t r0 = pbase + (w&3)*16 + g, r1 = r0 + 8;
  #pragma unroll
  for (int nb = 0; nb < 8; nb++){
    int col = (w>>2)*64 + nb*8 + tq*2;
    float b0 = kvbias[col], b1 = kvbias[col+1];
    *(uint32_t*)(kvout + r0*128 + col) = pack2(kacc[nb][0]+b0, kacc[nb][1]+b1);
    *(uint32_t*)(kvout + r1*128 + col) = pack2(kacc[nb][2]+b0, kacc[nb][3]+b1);
  }
}

// ---- attention (flash, 4 key chunks) + proj + residual + LN2 + fc1 ----
__global__ void __launch_bounds__(256, 2) attn_fused(
    const bf16* __restrict__ q, const bf16* __restrict__ kv,
    const bf16* __restrict__ wp, const float* __restrict__ pbias,
    const float* __restrict__ x, const float* __restrict__ g2,
    const float* __restrict__ b2, const bf16* __restrict__ w1,
    const float* __restrict__ fc1b, float* __restrict__ x2,
    bf16* __restrict__ fbout)
{
  extern __shared__ bf16 sma[];
  bf16* Qs = sma;              // 128 x 72
  bf16* Ks = sma + 128*72;     // 256 x 72 -> later w1 (64 x 264)
  bf16* Vs = Ks  + 256*72;     // 256 x 72
  bf16* Ps = Vs  + 256*72;     // 64 x 72
  int t = threadIdx.x, w = t>>5, lane = t&31;
  int b = blockIdx.y;
  size_t qrow0 = (size_t)b*NTOK + (size_t)blockIdx.x*128;
  const bf16* kvb = kv + (size_t)b*NRTOK*128;

  for (int i = t; i < 1024; i += 256){
    int r = i>>3, c8 = i&7;
    *(float4*)(Qs + r*72 + c8*8) = *(const float4*)(q + (qrow0 + r)*64 + c8*8);
  }
  for (int i = t; i < 2048; i += 256){
    int r = i>>3, c8 = i&7;
    *(float4*)(Ks + r*72 + c8*8) = *(const float4*)(kvb + (size_t)r*128 + c8*8);
  }
  for (int i = t; i < 2048; i += 256){
    int r = i>>3, c8 = i&7;
    *(float4*)(Vs + r*72 + c8*8) = *(const float4*)(kvb + (size_t)r*128 + 64 + c8*8);
  }
  for (int i = t; i < 512; i += 256){
    int r = i>>3, c8 = i&7;
    *(float4*)(Ps + r*72 + c8*8) = *(const float4*)(wp + r*64 + c8*8);
  }
  __syncthreads();

  uint32_t Qs_u = (uint32_t)__cvta_generic_to_shared(Qs);
  uint32_t Ks_u = (uint32_t)__cvta_generic_to_shared(Ks);
  uint32_t Vs_u = (uint32_t)__cvta_generic_to_shared(Vs);
  uint32_t Ps_u = (uint32_t)__cvta_generic_to_shared(Ps);
  uint32_t a_base = Qs_u + ((w*16 + (lane&15))*72 + (lane>>4)*8)*2;
  uint32_t k_off = ((((lane>>4)&1)*8 + (lane&7)))*144 + ((lane>>3)&1)*16;
  uint32_t v_off = (lane&15)*144 + (lane>>4)*16;

  uint32_t af[4][4];
  #pragma unroll
  for (int kb = 0; kb < 4; kb++) ldsm_x4(af[kb], a_base + kb*32);

  float oo[8][4];
  #pragma unroll
  for (int nb = 0; nb < 8; nb++){ oo[nb][0]=oo[nb][1]=oo[nb][2]=oo[nb][3]=0.f; }
  float m0 = -1e30f, m1 = -1e30f, l0 = 0.f, l1 = 0.f;

  #pragma unroll
  for (int c = 0; c < 4; c++){
    float s[8][4];
    #pragma unroll
    for (int nb = 0; nb < 8; nb++){ s[nb][0]=s[nb][1]=s[nb][2]=s[nb][3]=0.f; }
    #pragma unroll
    for (int kb = 0; kb < 4; kb++){
      #pragma unroll
      for (int ng = 0; ng < 4; ng++){
        uint32_t bb[4];
        ldsm_x4(bb, Ks_u + (uint32_t)((c*4 + ng)*16)*144 + kb*32 + k_off);
        mma_bf16(s[2*ng  ][0],s[2*ng  ][1],s[2*ng  ][2],s[2*ng  ][3],
                 af[kb][0],af[kb][1],af[kb][2],af[kb][3], bb[0],bb[1]);
        mma_bf16(s[2*ng+1][0],s[2*ng+1][1],s[2*ng+1][2],s[2*ng+1][3],
                 af[kb][0],af[kb][1],af[kb][2],af[kb][3], bb[2],bb[3]);
      }
    }
    float cm0 = -1e30f, cm1 = -1e30f;
    #pragma unroll
    for (int nb = 0; nb < 8; nb++){
      cm0 = fmaxf(cm0, fmaxf(s[nb][0], s[nb][1]));
      cm1 = fmaxf(cm1, fmaxf(s[nb][2], s[nb][3]));
    }
    cm0 = fmaxf(cm0, __shfl_xor_sync(0xffffffffu, cm0, 1));
    cm0 = fmaxf(cm0, __shfl_xor_sync(0xffffffffu, cm0, 2));
    cm1 = fmaxf(cm1, __shfl_xor_sync(0xffffffffu, cm1, 1));
    cm1 = fmaxf(cm1, __shfl_xor_sync(0xffffffffu, cm1, 2));
    float nm0 = fmaxf(m0, cm0), nm1 = fmaxf(m1, cm1);
    float sc0 = __expf(m0 - nm0), sc1 = __expf(m1 - nm1);
    m0 = nm0; m1 = nm1;
    float cs0 = 0.f, cs1 = 0.f;
    #pragma unroll
    for (int nb = 0; nb < 8; nb++){
      s[nb][0] = __expf(s[nb][0] - m0); cs0 += s[nb][0];
      s[nb][1] = __expf(s[nb][1] - m0); cs0 += s[nb][1];
      s[nb][2] = __expf(s[nb][2] - m1); cs1 += s[nb][2];
      s[nb][3] = __expf(s[nb][3] - m1); cs1 += s[nb][3];
    }
    l0 = l0*sc0 + cs0;
    l1 = l1*sc1 + cs1;
    #pragma unroll
    for (int nb = 0; nb < 8; nb++){
      oo[nb][0] *= sc0; oo[nb][1] *= sc0; oo[nb][2] *= sc1; oo[nb][3] *= sc1;
    }
    #pragma unroll
    for (int j = 0; j < 2; j++){
      uint32_t a0 = pack2(s[4*j  ][0], s[4*j  ][1]);
      uint32_t a1 = pack2(s[4*j  ][2], s[4*j  ][3]);
      uint32_t a2 = pack2(s[4*j+1][0], s[4*j+1][1]);
      uint32_t a3 = pack2(s[4*j+1][2], s[4*j+1][3]);
      uint32_t c0 = pack2(s[4*j+2][0], s[4*j+2][1]);
      uint32_t c1 = pack2(s[4*j+2][2], s[4*j+2][3]);
      uint32_t c2 = pack2(s[4*j+3][0], s[4*j+3][1]);
      uint32_t c3 = pack2(s[4*j+3][2], s[4*j+3][3]);
      uint32_t base0 = Vs_u + (uint32_t)(c*64 + j*32)*144 + v_off;
      uint32_t base1 = base0 + 16*144;
      #pragma unroll
      for (int n2 = 0; n2 < 4; n2++){
        uint32_t bb[4];
        ldsm_x4_t(bb, base0 + n2*32);
        mma_bf16(oo[2*n2  ][0],oo[2*n2  ][1],oo[2*n2  ][2],oo[2*n2  ][3],
                 a0,a1,a2,a3, bb[0],bb[1]);
        mma_bf16(oo[2*n2+1][0],oo[2*n2+1][1],oo[2*n2+1][2],oo[2*n2+1][3],
                 a0,a1,a2,a3, bb[2],bb[3]);
        ldsm_x4_t(bb, base1 + n2*32);
        mma_bf16(oo[2*n2  ][0],oo[2*n2  ][1],oo[2*n2  ][2],oo[2*n2  ][3],
                 c0,c1,c2,c3, bb[0],bb[1]);
        mma_bf16(oo[2*n2+1][0],oo[2*n2+1][1],oo[2*n2+1][2],oo[2*n2+1][3],
                 c0,c1,c2,c3, bb[2],bb[3]);
      }
    }
  }

  l0 += __shfl_xor_sync(0xffffffffu, l0, 1);
  l0 += __shfl_xor_sync(0xffffffffu, l0, 2);
  l1 += __shfl_xor_sync(0xffffffffu, l1, 1);
  l1 += __shfl_xor_sync(0xffffffffu, l1, 2);
  float inv0 = __frcp_rn(l0), inv1 = __frcp_rn(l1);
  #pragma unroll
  for (int nb = 0; nb < 8; nb++){
    oo[nb][0] *= inv0; oo[nb][1] *= inv0; oo[nb][2] *= inv1; oo[nb][3] *= inv1;
  }

  __syncthreads();
  for (int i = t; i < 2048; i += 256){
    int row = i>>5, c8 = i&31;
    cp_async16(Ks_u + (uint32_t)(row*264 + c8*8)*2, w1 + (size_t)row*256 + c8*8);
  }
  cp_async_commit();

  float acc2[8][4];
  #pragma unroll
  for (int nb = 0; nb < 8; nb++){ acc2[nb][0]=acc2[nb][1]=acc2[nb][2]=acc2[nb][3]=0.f; }
  #pragma unroll
  for (int kb = 0; kb < 4; kb++){
    uint32_t a0 = pack2(oo[2*kb  ][0], oo[2*kb  ][1]);
    uint32_t a1 = pack2(oo[2*kb  ][2], oo[2*kb  ][3]);
    uint32_t a2 = pack2(oo[2*kb+1][0], oo[2*kb+1][1]);
    uint32_t a3 = pack2(oo[2*kb+1][2], oo[2*kb+1][3]);
    uint32_t brow = Ps_u + (uint32_t)kb*16*144 + v_off;
    #pragma unroll
    for (int n2 = 0; n2 < 4; n2++){
      uint32_t bb[4];
      ldsm_x4_t(bb, brow + n2*32);
      mma_bf16(acc2[2*n2  ][0],acc2[2*n2  ][1],acc2[2*n2  ][2],acc2[2*n2  ][3],
               a0,a1,a2,a3, bb[0],bb[1]);
      mma_bf16(acc2[2*n2+1][0],acc2[2*n2+1][1],acc2[2*n2+1][2],acc2[2*n2+1][3],
               a0,a1,a2,a3, bb[2],bb[3]);
    }
  }

  int g = lane>>2, tq = lane&3;
  size_t r0 = qrow0 + w*16 + g, r1 = r0 + 8;
  float v0[16], v1[16];
  float s0 = 0.f, s1 = 0.f;
  #pragma unroll
  for (int nb = 0; nb < 8; nb++){
    int col = nb*8 + tq*2;
    float pb0 = pbias[col], pb1 = pbias[col+1];
    float2 xx0 = *(const float2*)(x + r0*64 + col);
    float2 xx1 = *(const float2*)(x + r1*64 + col);
    v0[2*nb]   = acc2[nb][0] + pb0 + xx0.x;
    v0[2*nb+1] = acc2[nb][1] + pb1 + xx0.y;
    v1[2*nb]   = acc2[nb][2] + pb0 + xx1.x;
    v1[2*nb+1] = acc2[nb][3] + pb1 + xx1.y;
    s0 += v0[2*nb] + v0[2*nb+1];
    s1 += v1[2*nb] + v1[2*nb+1];
  }
  s0 += __shfl_xor_sync(0xffffffffu, s0, 1);
  s0 += __shfl_xor_sync(0xffffffffu, s0, 2);
  s1 += __shfl_xor_sync(0xffffffffu, s1, 1);
  s1 += __shfl_xor_sync(0xffffffffu, s1, 2);
  float m0e = s0*(1.0f/64.0f), m1e = s1*(1.0f/64.0f);
  float q0 = 0.f, q1 = 0.f;
  #pragma unroll
  for (int j = 0; j < 16; j++){
    float d0 = v0[j]-m0e, d1 = v1[j]-m1e;
    q0 += d0*d0; q1 += d1*d1;
  }
  q0 += __shfl_xor_sync(0xffffffffu, q0, 1);
  q0 += __shfl_xor_sync(0xffffffffu, q0, 2);
  q1 += __shfl_xor_sync(0xffffffffu, q1, 1);
  q1 += __shfl_xor_sync(0xffffffffu, q1, 2);
  float rs0 = rsqrtf(q0*(1.0f/64.0f) + 1e-5f);
  float rs1 = rsqrtf(q1*(1.0f/64.0f) + 1e-5f);

  float hn0[16], hn1[16];
  #pragma unroll
  for (int nb = 0; nb < 8; nb++){
    int col = nb*8 + tq*2;
    *(float2*)(x2 + r0*64 + col) = make_float2(v0[2*nb], v0[2*nb+1]);
    *(float2*)(x2 + r1*64 + col) = make_float2(v1[2*nb], v1[2*nb+1]);
    float2 gg = *(const float2*)(g2 + col);
    float2 bb = *(const float2*)(b2 + col);
    hn0[2*nb]   = (v0[2*nb]  -m0e)*rs0*gg.x + bb.x;
    hn0[2*nb+1] = (v0[2*nb+1]-m0e)*rs0*gg.y + bb.y;
    hn1[2*nb]   = (v1[2*nb]  -m1e)*rs1*gg.x + bb.x;
    hn1[2*nb+1] = (v1[2*nb+1]-m1e)*rs1*gg.y + bb.y;
  }

  cp_async_wait0();
  __syncthreads();
  uint32_t b_off1 = (lane&15)*528 + (lane>>4)*16;
  #pragma unroll
  for (int h = 0; h < 2; h++){
    float fa[16][4];
    #pragma unroll
    for (int nb = 0; nb < 16; nb++){ fa[nb][0]=fa[nb][1]=fa[nb][2]=fa[nb][3]=0.f; }
    #pragma unroll
    for (int kb = 0; kb < 4; kb++){
      uint32_t a0 = pack2(hn0[4*kb],   hn0[4*kb+1]);
      uint32_t a1 = pack2(hn1[4*kb],   hn1[4*kb+1]);
      uint32_t a2 = pack2(hn0[4*kb+2], hn0[4*kb+3]);
      uint32_t a3 = pack2(hn1[4*kb+2], hn1[4*kb+3]);
      uint32_t brow = Ks_u + (uint32_t)(kb*16)*528 + h*256 + b_off1;
      #pragma unroll
      for (int n2 = 0; n2 < 8; n2++){
        uint32_t bb[4];
        ldsm_x4_t(bb, brow + n2*32);
        mma_bf16(fa[2*n2  ][0],fa[2*n2  ][1],fa[2*n2  ][2],fa[2*n2  ][3],
                 a0,a1,a2,a3, bb[0],bb[1]);
        mma_bf16(fa[2*n2+1][0],fa[2*n2+1][1],fa[2*n2+1][2],fa[2*n2+1][3],
                 a0,a1,a2,a3, bb[2],bb[3]);
      }
    }
    #pragma unroll
    for (int nb = 0; nb < 16; nb++){
      int col = h*128 + nb*8 + tq*2;
      float b0 = fc1b[col], b1 = fc1b[col+1];
      *(uint32_t*)(fbout + r0*256 + col) = pack2(fa[nb][0]+b0, fa[nb][1]+b1);
      *(uint32_t*)(fbout + r1*256 + col) = pack2(fa[nb][2]+b0, fa[nb][3]+b1);
    }
  }
}

// ---------------- fused dwconv3x3 + GELU + fc2 + residual ----------------
__global__ void __launch_bounds__(256, 2) fc2_fused(
    const bf16* __restrict__ f, const float* __restrict__ dw,
    const bf16* __restrict__ w2, const float* __restrict__ bias2,
    const float* __restrict__ x2, float* __restrict__ out)
{
  extern __shared__ bf16 smf[];
  bf16* Ws = smf;                 // 256 x 72
  bf16* Fs = smf + 256*72;        // 3 x 128 x 72
  bf16* Gs = Fs  + 3*128*72;      // 128 x 72
  int t = threadIdx.x, w = t>>5, lane = t&31;
  int by = blockIdx.x;
  int b = by >> 7, y = by & 127;
  size_t tokbase = (size_t)b*NTOK + (size_t)y*128;

  for (int i = t; i < 2048; i += 256){
    int row = i>>3, c8 = i&7;
    *(float4*)(Ws + row*72 + c8*8) = *(const float4*)(w2 + row*64 + c8*8);
  }

  float acc[8][4];
  #pragma unroll
  for (int nb = 0; nb < 8; nb++){ acc[nb][0]=acc[nb][1]=acc[nb][2]=acc[nb][3]=0.f; }
  uint32_t Ws_u = (uint32_t)__cvta_generic_to_shared(Ws);
  uint32_t Gs_u = (uint32_t)__cvta_generic_to_shared(Gs);
  uint32_t a_base = Gs_u + ((w*16 + (lane&15))*72 + (lane>>4)*8)*2;
  uint32_t b_off  = (lane&15)*144 + (lane>>4)*16;

  int chl = lane*2;
  int px0 = w*16;

  for (int kc = 0; kc < 256; kc += 64){
    __syncthreads();
    for (int i = t; i < 3072; i += 256){
      int row3 = i>>10, rem = i&1023, px = rem>>3, c8 = rem&7;
      int yy = y + row3 - 1;
      float4 val;
      if (yy >= 0 && yy < 128)
        val = *(const float4*)(f + ((size_t)b*NTOK + (size_t)yy*128 + px)*256 + kc + c8*8);
      else
        val = make_float4(0.f,0.f,0.f,0.f);
      *(float4*)(Fs + row3*9216 + px*72 + c8*8) = val;
    }
    __syncthreads();
    {
      float w9[2][9];
      #pragma unroll
      for (int i = 0; i < 9; i++){
        float2 wv = *(const float2*)(dw + i*256 + kc + chl);
        w9[0][i] = wv.x; w9[1][i] = wv.y;
      }
      float2 fv[3][3];   // [dx][dy], each float2 = 2 channels
      #pragma unroll
      for (int dy = 0; dy < 3; dy++){
        uint32_t u0 = (px0 > 0) ? *(uint32_t*)(Fs + dy*9216 + (px0-1)*72 + chl) : 0u;
        uint32_t u1 = *(uint32_t*)(Fs + dy*9216 + px0*72 + chl);
        fv[0][dy] = __bfloat1622float2(*reinterpret_cast<const __nv_bfloat162*>(&u0));
        fv[1][dy] = __bfloat1622float2(*reinterpret_cast<const __nv_bfloat162*>(&u1));
      }
      #pragma unroll
      for (int pi = 0; pi < 16; pi++){
        int px = px0 + pi;
        #pragma unroll
        for (int dy = 0; dy < 3; dy++){
          uint32_t u = (px+1 < 128) ? *(uint32_t*)(Fs + dy*9216 + (px+1)*72 + chl) : 0u;
          fv[2][dy] = __bfloat1622float2(*reinterpret_cast<const __nv_bfloat162*>(&u));
        }
        float a0 = 0.f, a1 = 0.f;
        #pragma unroll
        for (int dy = 0; dy < 3; dy++)
          #pragma unroll
          for (int dx = 0; dx < 3; dx++){
            a0 = fmaf(fv[dx][dy].x, w9[0][dy*3+dx], a0);
            a1 = fmaf(fv[dx][dy].y, w9[1][dy*3+dx], a1);
          }
        a0 = 0.5f*a0*(1.0f + erff(a0*0.70710678118654752f));
        a1 = 0.5f*a1*(1.0f + erff(a1*0.70710678118654752f));
        *(uint32_t*)(Gs + px*72 + chl) = pack2(a0, a1);
        #pragma unroll
        for (int dy = 0; dy < 3; dy++){ fv[0][dy] = fv[1][dy]; fv[1][dy] = fv[2][dy]; }
      }
    }
    __syncwarp();
    #pragma unroll
    for (int kb = 0; kb < 4; kb++){
      uint32_t a[4];
      ldsm_x4(a, a_base + kb*32);
      uint32_t brow = Ws_u + (uint32_t)(kc + kb*16)*144 + b_off;
      #pragma unroll
      for (int n2 = 0; n2 < 4; n2++){
        uint32_t bb[4];
        ldsm_x4_t(bb, brow + n2*32);
        mma_bf16(acc[2*n2  ][0],acc[2*n2  ][1],acc[2*n2  ][2],acc[2*n2  ][3],
                 a[0],a[1],a[2],a[3], bb[0],bb[1]);
        mma_bf16(acc[2*n2+1][0],acc[2*n2+1][1],acc[2*n2+1][2],acc[2*n2+1][3],
                 a[0],a[1],a[2],a[3], bb[2],bb[3]);
      }
    }
  }

  int g = lane>>2, tq = lane&3;
  size_t r0 = tokbase + w*16 + g, r1 = r0 + 8;
  #pragma unroll
  for (int nb = 0; nb < 8; nb++){
    int col = nb*8 + tq*2;
    float b0 = bias2[col], b1 = bias2[col+1];
    float2 q0 = *(const float2*)(x2 + r0*64 + col);
    float2 q1 = *(const float2*)(x2 + r1*64 + col);
    *(float2*)(out + r0*64 + col) = make_float2(acc[nb][0]+b0+q0.x, acc[nb][1]+b1+q0.y);
    *(float2*)(out + r1*64 + col) = make_float2(acc[nb][2]+b0+q1.x, acc[nb][3]+b1+q1.y);
  }
}

// ---------------- launch ----------------
extern "C" void kernel_launch(void* const* d_in, const int* in_sizes, int n_in,
                              void* d_out, int out_size)
{
  const float* x      = (const float*)d_in[0];
  const float* ln1_g  = (const float*)d_in[3];
  const float* ln1_b  = (const float*)d_in[4];
  const float* q_w    = (const float*)d_in[5];
  const float* q_b    = (const float*)d_in[6];
  const float* kv_w   = (const float*)d_in[7];
  const float* kv_b   = (const float*)d_in[8];
  const float* proj_w = (const float*)d_in[9];
  const float* proj_b = (const float*)d_in[10];
  const float* sr_w   = (const float*)d_in[11];
  const float* sr_b   = (const float*)d_in[12];
  const float* srn_g  = (const float*)d_in[13];
  const float* srn_b  = (const float*)d_in[14];
  const float* ln2_g  = (const float*)d_in[15];
  const float* ln2_b  = (const float*)d_in[16];
  const float* fc1_w  = (const float*)d_in[17];
  const float* fc1_b  = (const float*)d_in[18];
  const float* dw_w   = (const float*)d_in[19];
  const float* fc2_w  = (const float*)d_in[20];
  const float* fc2_b  = (const float*)d_in[21];
  float* out = (float*)d_out;

  bf16 *hb,*qb,*fb,*kvbuf,*wq,*wkv,*wp,*wsr,*w1,*w2;
  float *x2;
  cudaGetSymbolAddress((void**)&hb,  g_hb);
  cudaGetSymbolAddress((void**)&qb,  g_qb);
  cudaGetSymbolAddress((void**)&x2,  g_x2);
  cudaGetSymbolAddress((void**)&fb,  g_fb);
  cudaGetSymbolAddress((void**)&kvbuf, g_kvb);
  cudaGetSymbolAddress((void**)&wq,  g_wq);
  cudaGetSymbolAddress((void**)&wkv, g_wkv);
  cudaGetSymbolAddress((void**)&wp,  g_wp);
  cudaGetSymbolAddress((void**)&wsr, g_wsr);
  cudaGetSymbolAddress((void**)&w1,  g_w1);
  cudaGetSymbolAddress((void**)&w2,  g_w2);

  const int SM_ATTN = (128 + 256 + 256 + 64)*72*2;    // 101376
  const int SM_FC2  = (256 + 3*128 + 128)*72*2;       // 110592

  cudaFuncSetAttribute((const void*)spatial_kv,
                       cudaFuncAttributeMaxDynamicSharedMemorySize, SKV_SMEM);
  cudaFuncSetAttribute((const void*)attn_fused,
                       cudaFuncAttributeMaxDynamicSharedMemorySize, SM_ATTN);
  cudaFuncSetAttribute((const void*)fc2_fused,
                       cudaFuncAttributeMaxDynamicSharedMemorySize, SM_FC2);

  CvtArgs ca = { q_w, kv_w, proj_w, sr_w, fc1_w, fc2_w, wq, wkv, wp, wsr, w1, w2 };
  cvt_all<<<1216, 256>>>(ca);
  ln1q_kernel<<<1024, 256>>>(x, wq, q_b, ln1_g, ln1_b, hb, qb);
  spatial_kv<<<32, 256, SKV_SMEM>>>(hb, wsr, sr_b, srn_g, srn_b, wkv, kv_b, kvbuf);
  attn_fused<<<dim3(128, BB), 256, SM_ATTN>>>(qb, kvbuf, wp, proj_b, x,
                                              ln2_g, ln2_b, w1, fc1_b, x2, fb);
  fc2_fused<<<1024, 256, SM_FC2>>>(fb, dw_w, w2, fc2_b, x2, out);
}

// round 9
// speedup vs baseline: 1.0111x; 1.0111x over previous
#include <cuda_runtime.h>
#include <cuda_bf16.h>
#include <math.h>
#include <stdint.h>

typedef __nv_bfloat16 bf16;

#define BB    8
#define NTOK  16384
#define CC    64
#define HIDD  256
#define NRTOK 256
#define MTOT  (BB*NTOK)   // 131072

// ---------------- scratch ----------------
__device__ bf16  g_hb [(size_t)MTOT*CC];
__device__ float g_x2 [(size_t)MTOT*CC];
__device__ bf16  g_fb [(size_t)MTOT*HIDD];
__device__ bf16  g_kvb[(size_t)2048*2*CC];
__device__ bf16  g_wq [64*64];
__device__ bf16  g_wkv[64*128];
__device__ bf16  g_wp [64*64];
__device__ bf16  g_wsr[4096*64];
__device__ bf16  g_w1 [64*256];
__device__ bf16  g_w2 [256*64];

// ---------------- helpers ----------------
__device__ __forceinline__ void mma_bf16(float& d0,float& d1,float& d2,float& d3,
    uint32_t a0,uint32_t a1,uint32_t a2,uint32_t a3,uint32_t b0,uint32_t b1){
  asm volatile("mma.sync.aligned.m16n8k16.row.col.f32.bf16.bf16.f32 "
    "{%0,%1,%2,%3}, {%4,%5,%6,%7}, {%8,%9}, {%0,%1,%2,%3};\n"
    : "+f"(d0),"+f"(d1),"+f"(d2),"+f"(d3)
    : "r"(a0),"r"(a1),"r"(a2),"r"(a3),"r"(b0),"r"(b1));
}
__device__ __forceinline__ void ldsm_x4(uint32_t* r, uint32_t addr){
  asm volatile("ldmatrix.sync.aligned.m8n8.x4.shared.b16 {%0,%1,%2,%3}, [%4];\n"
    : "=r"(r[0]),"=r"(r[1]),"=r"(r[2]),"=r"(r[3]) : "r"(addr));
}
__device__ __forceinline__ void ldsm_x4_t(uint32_t* r, uint32_t addr){
  asm volatile("ldmatrix.sync.aligned.m8n8.x4.trans.shared.b16 {%0,%1,%2,%3}, [%4];\n"
    : "=r"(r[0]),"=r"(r[1]),"=r"(r[2]),"=r"(r[3]) : "r"(addr));
}
__device__ __forceinline__ uint32_t pack2(float lo, float hi){
  __nv_bfloat162 v = __floats2bfloat162_rn(lo, hi);
  return reinterpret_cast<uint32_t&>(v);
}
__device__ __forceinline__ void cp_async16(uint32_t saddr, const void* gptr){
  asm volatile("cp.async.ca.shared.global [%0], [%1], 16;\n" :: "r"(saddr), "l"(gptr));
}
__device__ __forceinline__ void cp_async_commit(){ asm volatile("cp.async.commit_group;\n"); }
__device__ __forceinline__ void cp_async_wait0(){ asm volatile("cp.async.wait_group 0;\n"); }
__device__ __forceinline__ void cp_async_wait1(){ asm volatile("cp.async.wait_group 1;\n"); }

// ---------------- weight conversions ----------------
struct CvtArgs {
  const float* s0; const float* s1; const float* s2;
  const float* s3; const float* s4; const float* s5;
  bf16 *d0,*d1,*d2,*d3,*d4,*d5;
};
__global__ void __launch_bounds__(256) cvt_all(CvtArgs a){
  int i = blockIdx.x*256 + threadIdx.x;
  if (i < 4096)                { a.d0[i] = __float2bfloat16(a.s0[i]); return; }
  if (i < 12288)               { int j=i-4096;   a.d1[j] = __float2bfloat16(a.s1[j]); return; }
  if (i < 16384)               { int j=i-12288;  a.d2[j] = __float2bfloat16(a.s2[j]); return; }
  if (i < 278528)              { int j=i-16384;  a.d3[j] = __float2bfloat16(a.s3[j]); return; }
  if (i < 294912)              { int j=i-278528; a.d4[j] = __float2bfloat16(a.s4[j]); return; }
  if (i < 311296)              { int j=i-294912; a.d5[j] = __float2bfloat16(a.s5[j]); return; }
}

// ---------------- LN1 (pure): x fp32 -> hb bf16 ----------------
__global__ void __launch_bounds__(256) ln1_kernel(
    const float* __restrict__ x, const float* __restrict__ g1,
    const float* __restrict__ b1, bf16* __restrict__ hb)
{
  size_t rowbase = (size_t)blockIdx.x * 128;
  int t = threadIdx.x;
  int r = t>>1, half = t&1, col0 = half*32;
  const float* xr = x + (rowbase + r)*64 + col0;
  float v[32];
  #pragma unroll
  for (int j = 0; j < 8; j++) *(float4*)(v + j*4) = *(const float4*)(xr + j*4);
  float s = 0.f;
  #pragma unroll
  for (int j = 0; j < 32; j++) s += v[j];
  s += __shfl_xor_sync(0xffffffffu, s, 1);
  float mean = s * (1.0f/64.0f);
  float qv = 0.f;
  #pragma unroll
  for (int j = 0; j < 32; j++){ float d = v[j]-mean; qv += d*d; }
  qv += __shfl_xor_sync(0xffffffffu, qv, 1);
  float rstd = rsqrtf(qv*(1.0f/64.0f) + 1e-5f);
  #pragma unroll
  for (int j = 0; j < 16; j++){
    int c = col0 + 2*j;
    float2 gg = *(const float2*)(g1 + c);
    float2 bb = *(const float2*)(b1 + c);
    *(uint32_t*)(hb + (rowbase + r)*64 + c) =
        pack2((v[2*j]-mean)*rstd*gg.x + bb.x, (v[2*j+1]-mean)*rstd*gg.y + bb.y);
  }
}

// ---- fused sr-conv (full K, cp.async double buffered) + srn-LN + kv GEMM ----
#define SKV_SMEM (54272 + 64*68*4)
__global__ void __launch_bounds__(256) spatial_kv(
    const bf16* __restrict__ h, const bf16* __restrict__ wsr,
    const float* __restrict__ srb, const float* __restrict__ gamma,
    const float* __restrict__ beta, const bf16* __restrict__ wkv,
    const float* __restrict__ kvbias, bf16* __restrict__ kvout)
{
  extern __shared__ bf16 smk[];
  bf16* Wkv = smk;
  float* Cs = (float*)((char*)smk + 54272);
  int t = threadIdx.x, w = t>>5, lane = t&31;
  int pbase = blockIdx.x * 64;
  uint32_t base_u = (uint32_t)__cvta_generic_to_shared(smk);

  for (int i = t; i < 1024; i += 256){
    int row = i>>4, c8 = i&15;
    *(float4*)(Wkv + row*136 + c8*8) = *(const float4*)(wkv + row*128 + c8*8);
  }

  auto stage = [&](int kk, int s){
    int r1 = kk>>3, c2 = kk&7;
    #pragma unroll
    for (int i = t; i < 512; i += 256){
      int pl = i>>3, c8 = i&7;
      int p = pbase + pl;
      int b = p>>8, ph = (p>>4)&15, pw = p&15;
      const bf16* src = h + (((size_t)b*128 + ph*8 + r1)*128 + pw*8 + c2)*64 + c8*8;
      cp_async16(base_u + (uint32_t)((8704 + s*4608) + pl*72 + c8*8)*2, src);
    }
    #pragma unroll
    for (int i = t; i < 512; i += 256){
      int row = i>>3, c8 = i&7;
      const bf16* src = wsr + ((size_t)kk*64 + row)*64 + c8*8;
      cp_async16(base_u + (uint32_t)((17920 + s*4608) + row*72 + c8*8)*2, src);
    }
    cp_async_commit();
  };

  float acc[4][4];
  #pragma unroll
  for (int nb = 0; nb < 4; nb++){ acc[nb][0]=acc[nb][1]=acc[nb][2]=acc[nb][3]=0.f; }
  uint32_t a_off = (((w&3)*16 + (lane&15))*72 + (lane>>4)*8)*2;
  uint32_t b_off = (lane&15)*144 + (lane>>4)*16 + (w>>2)*64;

  stage(0, 0);
  for (int kk = 0; kk < 64; kk++){
    int cur = kk & 1;
    if (kk < 63) stage(kk+1, 1-cur);
    if (kk < 63) cp_async_wait1(); else cp_async_wait0();
    __syncthreads();
    uint32_t Abase = base_u + (uint32_t)(8704 + cur*4608)*2;
    uint32_t Wbase = base_u + (uint32_t)(17920 + cur*4608)*2;
    #pragma unroll
    for (int kb = 0; kb < 4; kb++){
      uint32_t a[4];
      ldsm_x4(a, Abase + a_off + kb*32);
      uint32_t brow = Wbase + (uint32_t)(kb*16)*144 + b_off;
      #pragma unroll
      for (int n2 = 0; n2 < 2; n2++){
        uint32_t b[4];
        ldsm_x4_t(b, brow + n2*32);
        mma_bf16(acc[2*n2  ][0],acc[2*n2  ][1],acc[2*n2  ][2],acc[2*n2  ][3],
                 a[0],a[1],a[2],a[3], b[0],b[1]);
        mma_bf16(acc[2*n2+1][0],acc[2*n2+1][1],acc[2*n2+1][2],acc[2*n2+1][3],
                 a[0],a[1],a[2],a[3], b[2],b[3]);
      }
    }
    __syncthreads();
  }

  {
    int g = lane>>2, tq = lane&3;
    int row0 = (w&3)*16 + g;
    #pragma unroll
    for (int nb = 0; nb < 4; nb++){
      int col = (w>>2)*32 + nb*8 + tq*2;
      *(float2*)(Cs + row0*68 + col)     = make_float2(acc[nb][0], acc[nb][1]);
      *(float2*)(Cs + (row0+8)*68 + col) = make_float2(acc[nb][2], acc[nb][3]);
    }
  }
  __syncthreads();

  bf16* As = smk + 8704;
  if (t < 128){
    int r = t>>1, half = t&1, col0 = half*32;
    float v[32];
    #pragma unroll
    for (int j = 0; j < 32; j++) v[j] = Cs[r*68 + col0 + j] + srb[col0 + j];
    float s = 0.f;
    #pragma unroll
    for (int j = 0; j < 32; j++) s += v[j];
    s += __shfl_xor_sync(0xffffffffu, s, 1);
    float mean = s * (1.0f/64.0f);
    float qv = 0.f;
    #pragma unroll
    for (int j = 0; j < 32; j++){ float d = v[j]-mean; qv += d*d; }
    qv += __shfl_xor_sync(0xffffffffu, qv, 1);
    float rstd = rsqrtf(qv*(1.0f/64.0f) + 1e-5f);
    #pragma unroll
    for (int j = 0; j < 16; j++){
      int c = col0 + 2*j;
      float2 gg = *(const float2*)(gamma + c);
      float2 bb = *(const float2*)(beta + c);
      *(uint32_t*)(As + r*72 + c) = pack2((v[2*j]-mean)*rstd*gg.x + bb.x,
                                          (v[2*j+1]-mean)*rstd*gg.y + bb.y);
    }
  }
  __syncthreads();

  float kacc[8][4];
  #pragma unroll
  for (int nb = 0; nb < 8; nb++){ kacc[nb][0]=kacc[nb][1]=kacc[nb][2]=kacc[nb][3]=0.f; }
  uint32_t As_u = base_u + 8704*2;
  uint32_t Wk_u = base_u;
  uint32_t a2_base = As_u + (((w&3)*16 + (lane&15))*72 + (lane>>4)*8)*2;
  uint32_t b2_off  = (lane&15)*272 + (lane>>4)*16 + (w>>2)*128;
  #pragma unroll
  for (int kb = 0; kb < 4; kb++){
    uint32_t a[4];
    ldsm_x4(a, a2_base + kb*32);
    uint32_t brow = Wk_u + (uint32_t)(kb*16)*272 + b2_off;
    #pragma unroll
    for (int n2 = 0; n2 < 4; n2++){
      uint32_t b[4];
      ldsm_x4_t(b, brow + n2*32);
      mma_bf16(kacc[2*n2  ][0],kacc[2*n2  ][1],kacc[2*n2  ][2],kacc[2*n2  ][3],
               a[0],a[1],a[2],a[3], b[0],b[1]);
      mma_bf16(kacc[2*n2+1][0],kacc[2*n2+1][1],kacc[2*n2+1][2],kacc[2*n2+1][3],
               a[0],a[1],a[2],a[3], b[2],b[3]);
    }
  }
  int g = lane>>2, tq = lane&3;
  size_t r0 = pbase + (w&3)*16 + g, r1 = r0 + 8;
  #pragma unroll
  for (int nb = 0; nb < 8; nb++){
    int col = (w>>2)*64 + nb*8 + tq*2;
    float b0 = kvbias[col], b1 = kvbias[col+1];
    *(uint32_t*)(kvout + r0*128 + col) = pack2(kacc[nb][0]+b0, kacc[nb][1]+b1);
    *(uint32_t*)(kvout + r1*128 + col) = pack2(kacc[nb][2]+b0, kacc[nb][3]+b1);
  }
}

// ---- attention: in-kernel qGEMM + flash + proj + residual + LN2 + fc1 ----
__global__ void __launch_bounds__(256, 2) attn_fused(
    const bf16* __restrict__ hb, const bf16* __restrict__ wq,
    const float* __restrict__ qbias, const bf16* __restrict__ kv,
    const bf16* __restrict__ wp, const float* __restrict__ pbias,
    const float* __restrict__ x, const float* __restrict__ g2,
    const float* __restrict__ b2, const bf16* __restrict__ w1,
    const float* __restrict__ fc1b, float* __restrict__ x2,
    bf16* __restrict__ fbout)
{
  extern __shared__ bf16 sma[];
  bf16* Qs = sma;              // 128 x 72: h tile, later hn (LN2 out)
  bf16* Ks = sma + 128*72;     // 256 x 72: K, later w1 (64 x 264)
  bf16* Vs = Ks  + 256*72;     // 256 x 72
  bf16* Ps = Vs  + 256*72;     // 64 x 72: wq, later wp
  int t = threadIdx.x, w = t>>5, lane = t&31;
  int b = blockIdx.y;
  size_t qrow0 = (size_t)b*NTOK + (size_t)blockIdx.x*128;
  const bf16* kvb = kv + (size_t)b*NRTOK*128;

  for (int i = t; i < 1024; i += 256){
    int r = i>>3, c8 = i&7;
    *(float4*)(Qs + r*72 + c8*8) = *(const float4*)(hb + (qrow0 + r)*64 + c8*8);
  }
  for (int i = t; i < 2048; i += 256){
    int r = i>>3, c8 = i&7;
    *(float4*)(Ks + r*72 + c8*8) = *(const float4*)(kvb + (size_t)r*128 + c8*8);
  }
  for (int i = t; i < 2048; i += 256){
    int r = i>>3, c8 = i&7;
    *(float4*)(Vs + r*72 + c8*8) = *(const float4*)(kvb + (size_t)r*128 + 64 + c8*8);
  }
  for (int i = t; i < 512; i += 256){
    int r = i>>3, c8 = i&7;
    *(float4*)(Ps + r*72 + c8*8) = *(const float4*)(wq + r*64 + c8*8);
  }
  __syncthreads();

  uint32_t Qs_u = (uint32_t)__cvta_generic_to_shared(Qs);
  uint32_t Ks_u = (uint32_t)__cvta_generic_to_shared(Ks);
  uint32_t Vs_u = (uint32_t)__cvta_generic_to_shared(Vs);
  uint32_t Ps_u = (uint32_t)__cvta_generic_to_shared(Ps);
  uint32_t a_base = Qs_u + ((w*16 + (lane&15))*72 + (lane>>4)*8)*2;
  uint32_t k_off = ((((lane>>4)&1)*8 + (lane&7)))*144 + ((lane>>3)&1)*16;
  uint32_t v_off = (lane&15)*144 + (lane>>4)*16;
  int g = lane>>2, tq = lane&3;

  // ---- q = (h @ wq + qbias) * 0.125, a-fragments formed directly from acc ----
  uint32_t af[4][4];
  {
    float qa[8][4];
    #pragma unroll
    for (int nb = 0; nb < 8; nb++){ qa[nb][0]=qa[nb][1]=qa[nb][2]=qa[nb][3]=0.f; }
    #pragma unroll
    for (int kb = 0; kb < 4; kb++){
      uint32_t a[4];
      ldsm_x4(a, a_base + kb*32);
      uint32_t brow = Ps_u + (uint32_t)(kb*16)*144 + v_off;
      #pragma unroll
      for (int n2 = 0; n2 < 4; n2++){
        uint32_t bbq[4];
        ldsm_x4_t(bbq, brow + n2*32);
        mma_bf16(qa[2*n2  ][0],qa[2*n2  ][1],qa[2*n2  ][2],qa[2*n2  ][3],
                 a[0],a[1],a[2],a[3], bbq[0],bbq[1]);
        mma_bf16(qa[2*n2+1][0],qa[2*n2+1][1],qa[2*n2+1][2],qa[2*n2+1][3],
                 a[0],a[1],a[2],a[3], bbq[2],bbq[3]);
      }
    }
    #pragma unroll
    for (int kb = 0; kb < 4; kb++){
      int c0 = 16*kb + 2*tq, c1 = c0 + 8;
      float bq00 = qbias[c0], bq01 = qbias[c0+1];
      float bq10 = qbias[c1], bq11 = qbias[c1+1];
      af[kb][0] = pack2((qa[2*kb  ][0]+bq00)*0.125f, (qa[2*kb  ][1]+bq01)*0.125f);
      af[kb][1] = pack2((qa[2*kb  ][2]+bq00)*0.125f, (qa[2*kb  ][3]+bq01)*0.125f);
      af[kb][2] = pack2((qa[2*kb+1][0]+bq10)*0.125f, (qa[2*kb+1][1]+bq11)*0.125f);
      af[kb][3] = pack2((qa[2*kb+1][2]+bq10)*0.125f, (qa[2*kb+1][3]+bq11)*0.125f);
    }
  }
  // Ps dead: async-load wp into it
  __syncthreads();
  for (int i = t; i < 512; i += 256){
    int r = i>>3, c8 = i&7;
    cp_async16(Ps_u + (uint32_t)(r*72 + c8*8)*2, wp + (size_t)r*64 + c8*8);
  }
  cp_async_commit();   // group: wp

  float oo[8][4];
  #pragma unroll
  for (int nb = 0; nb < 8; nb++){ oo[nb][0]=oo[nb][1]=oo[nb][2]=oo[nb][3]=0.f; }
  float m0 = -1e30f, m1 = -1e30f, l0 = 0.f, l1 = 0.f;

  #pragma unroll
  for (int c = 0; c < 4; c++){
    float s[8][4];
    #pragma unroll
    for (int nb = 0; nb < 8; nb++){ s[nb][0]=s[nb][1]=s[nb][2]=s[nb][3]=0.f; }
    #pragma unroll
    for (int kb = 0; kb < 4; kb++){
      #pragma unroll
      for (int ng = 0; ng < 4; ng++){
        uint32_t bb[4];
        ldsm_x4(bb, Ks_u + (uint32_t)((c*4 + ng)*16)*144 + kb*32 + k_off);
        mma_bf16(s[2*ng  ][0],s[2*ng  ][1],s[2*ng  ][2],s[2*ng  ][3],
                 af[kb][0],af[kb][1],af[kb][2],af[kb][3], bb[0],bb[1]);
        mma_bf16(s[2*ng+1][0],s[2*ng+1][1],s[2*ng+1][2],s[2*ng+1][3],
                 af[kb][0],af[kb][1],af[kb][2],af[kb][3], bb[2],bb[3]);
      }
    }
    float cm0 = -1e30f, cm1 = -1e30f;
    #pragma unroll
    for (int nb = 0; nb < 8; nb++){
      cm0 = fmaxf(cm0, fmaxf(s[nb][0], s[nb][1]));
      cm1 = fmaxf(cm1, fmaxf(s[nb][2], s[nb][3]));
    }
    cm0 = fmaxf(cm0, __shfl_xor_sync(0xffffffffu, cm0, 1));
    cm0 = fmaxf(cm0, __shfl_xor_sync(0xffffffffu, cm0, 2));
    cm1 = fmaxf(cm1, __shfl_xor_sync(0xffffffffu, cm1, 1));
    cm1 = fmaxf(cm1, __shfl_xor_sync(0xffffffffu, cm1, 2));
    float nm0 = fmaxf(m0, cm0), nm1 = fmaxf(m1, cm1);
    float sc0 = __expf(m0 - nm0), sc1 = __expf(m1 - nm1);
    m0 = nm0; m1 = nm1;
    float cs0 = 0.f, cs1 = 0.f;
    #pragma unroll
    for (int nb = 0; nb < 8; nb++){
      s[nb][0] = __expf(s[nb][0] - m0); cs0 += s[nb][0];
      s[nb][1] = __expf(s[nb][1] - m0); cs0 += s[nb][1];
      s[nb][2] = __expf(s[nb][2] - m1); cs1 += s[nb][2];
      s[nb][3] = __expf(s[nb][3] - m1); cs1 += s[nb][3];
    }
    l0 = l0*sc0 + cs0;
    l1 = l1*sc1 + cs1;
    #pragma unroll
    for (int nb = 0; nb < 8; nb++){
      oo[nb][0] *= sc0; oo[nb][1] *= sc0; oo[nb][2] *= sc1; oo[nb][3] *= sc1;
    }
    #pragma unroll
    for (int j = 0; j < 2; j++){
      uint32_t a0 = pack2(s[4*j  ][0], s[4*j  ][1]);
      uint32_t a1 = pack2(s[4*j  ][2], s[4*j  ][3]);
      uint32_t a2 = pack2(s[4*j+1][0], s[4*j+1][1]);
      uint32_t a3 = pack2(s[4*j+1][2], s[4*j+1][3]);
      uint32_t c0 = pack2(s[4*j+2][0], s[4*j+2][1]);
      uint32_t c1 = pack2(s[4*j+2][2], s[4*j+2][3]);
      uint32_t c2 = pack2(s[4*j+3][0], s[4*j+3][1]);
      uint32_t c3 = pack2(s[4*j+3][2], s[4*j+3][3]);
      uint32_t base0 = Vs_u + (uint32_t)(c*64 + j*32)*144 + v_off;
      uint32_t base1 = base0 + 16*144;
      #pragma unroll
      for (int n2 = 0; n2 < 4; n2++){
        uint32_t bb[4];
        ldsm_x4_t(bb, base0 + n2*32);
        mma_bf16(oo[2*n2  ][0],oo[2*n2  ][1],oo[2*n2  ][2],oo[2*n2  ][3],
                 a0,a1,a2,a3, bb[0],bb[1]);
        mma_bf16(oo[2*n2+1][0],oo[2*n2+1][1],oo[2*n2+1][2],oo[2*n2+1][3],
                 a0,a1,a2,a3, bb[2],bb[3]);
        ldsm_x4_t(bb, base1 + n2*32);
        mma_bf16(oo[2*n2  ][0],oo[2*n2  ][1],oo[2*n2  ][2],oo[2*n2  ][3],
                 c0,c1,c2,c3, bb[0],bb[1]);
        mma_bf16(oo[2*n2+1][0],oo[2*n2+1][1],oo[2*n2+1][2],oo[2*n2+1][3],
                 c0,c1,c2,c3, bb[2],bb[3]);
      }
    }
  }

  l0 += __shfl_xor_sync(0xffffffffu, l0, 1);
  l0 += __shfl_xor_sync(0xffffffffu, l0, 2);
  l1 += __shfl_xor_sync(0xffffffffu, l1, 1);
  l1 += __shfl_xor_sync(0xffffffffu, l1, 2);
  float inv0 = __frcp_rn(l0), inv1 = __frcp_rn(l1);
  #pragma unroll
  for (int nb = 0; nb < 8; nb++){
    oo[nb][0] *= inv0; oo[nb][1] *= inv0; oo[nb][2] *= inv1; oo[nb][3] *= inv1;
  }

  // Ks dead: async-load w1 (64x256 -> stride 264)
  __syncthreads();
  for (int i = t; i < 2048; i += 256){
    int row = i>>5, c8 = i&31;
    cp_async16(Ks_u + (uint32_t)(row*264 + c8*8)*2, w1 + (size_t)row*256 + c8*8);
  }
  cp_async_commit();   // groups: wp, w1
  cp_async_wait1();    // wp landed (per-thread)
  __syncthreads();     // wp visible to all

  // proj GEMM (wp in Ps)
  float acc2[8][4];
  #pragma unroll
  for (int nb = 0; nb < 8; nb++){ acc2[nb][0]=acc2[nb][1]=acc2[nb][2]=acc2[nb][3]=0.f; }
  #pragma unroll
  for (int kb = 0; kb < 4; kb++){
    uint32_t a0 = pack2(oo[2*kb  ][0], oo[2*kb  ][1]);
    uint32_t a1 = pack2(oo[2*kb  ][2], oo[2*kb  ][3]);
    uint32_t a2 = pack2(oo[2*kb+1][0], oo[2*kb+1][1]);
    uint32_t a3 = pack2(oo[2*kb+1][2], oo[2*kb+1][3]);
    uint32_t brow = Ps_u + (uint32_t)kb*16*144 + v_off;
    #pragma unroll
    for (int n2 = 0; n2 < 4; n2++){
      uint32_t bb[4];
      ldsm_x4_t(bb, brow + n2*32);
      mma_bf16(acc2[2*n2  ][0],acc2[2*n2  ][1],acc2[2*n2  ][2],acc2[2*n2  ][3],
               a0,a1,a2,a3, bb[0],bb[1]);
      mma_bf16(acc2[2*n2+1][0],acc2[2*n2+1][1],acc2[2*n2+1][2],acc2[2*n2+1][3],
               a0,a1,a2,a3, bb[2],bb[3]);
    }
  }

  // epilogue: x2 = x + proj; LN2 -> Qs (hn), then fc1 via ldmatrix
  size_t r0 = qrow0 + w*16 + g, r1 = r0 + 8;
  {
    float v0[16], v1[16];
    float s0 = 0.f, s1 = 0.f;
    #pragma unroll
    for (int nb = 0; nb < 8; nb++){
      int col = nb*8 + tq*2;
      float pb0 = pbias[col], pb1 = pbias[col+1];
      float2 xx0 = *(const float2*)(x + r0*64 + col);
      float2 xx1 = *(const float2*)(x + r1*64 + col);
      v0[2*nb]   = acc2[nb][0] + pb0 + xx0.x;
      v0[2*nb+1] = acc2[nb][1] + pb1 + xx0.y;
      v1[2*nb]   = acc2[nb][2] + pb0 + xx1.x;
      v1[2*nb+1] = acc2[nb][3] + pb1 + xx1.y;
      s0 += v0[2*nb] + v0[2*nb+1];
      s1 += v1[2*nb] + v1[2*nb+1];
    }
    s0 += __shfl_xor_sync(0xffffffffu, s0, 1);
    s0 += __shfl_xor_sync(0xffffffffu, s0, 2);
    s1 += __shfl_xor_sync(0xffffffffu, s1, 1);
    s1 += __shfl_xor_sync(0xffffffffu, s1, 2);
    float m0e = s0*(1.0f/64.0f), m1e = s1*(1.0f/64.0f);
    float q0 = 0.f, q1 = 0.f;
    #pragma unroll
    for (int j = 0; j < 16; j++){
      float d0 = v0[j]-m0e, d1 = v1[j]-m1e;
      q0 += d0*d0; q1 += d1*d1;
    }
    q0 += __shfl_xor_sync(0xffffffffu, q0, 1);
    q0 += __shfl_xor_sync(0xffffffffu, q0, 2);
    q1 += __shfl_xor_sync(0xffffffffu, q1, 1);
    q1 += __shfl_xor_sync(0xffffffffu, q1, 2);
    float rs0 = rsqrtf(q0*(1.0f/64.0f) + 1e-5f);
    float rs1 = rsqrtf(q1*(1.0f/64.0f) + 1e-5f);
    int row0 = w*16 + g;
    #pragma unroll
    for (int nb = 0; nb < 8; nb++){
      int col = nb*8 + tq*2;
      *(float2*)(x2 + r0*64 + col) = make_float2(v0[2*nb], v0[2*nb+1]);
      *(float2*)(x2 + r1*64 + col) = make_float2(v1[2*nb], v1[2*nb+1]);
      float2 gg = *(const float2*)(g2 + col);
      float2 bb = *(const float2*)(b2 + col);
      *(uint32_t*)(Qs + row0*72 + col) =
          pack2((v0[2*nb]-m0e)*rs0*gg.x + bb.x, (v0[2*nb+1]-m0e)*rs0*gg.y + bb.y);
      *(uint32_t*)(Qs + (row0+8)*72 + col) =
          pack2((v1[2*nb]-m1e)*rs1*gg.x + bb.x, (v1[2*nb+1]-m1e)*rs1*gg.y + bb.y);
    }
  }
  __syncwarp();

  // fc1: f = hn @ w1 + fc1b (hn in Qs rows w*16..+15, w1 in Ks stride 264)
  cp_async_wait0();
  __syncthreads();
  uint32_t af1[4][4];
  #pragma unroll
  for (int kb = 0; kb < 4; kb++) ldsm_x4(af1[kb], a_base + kb*32);
  uint32_t b_off1 = (lane&15)*528 + (lane>>4)*16;
  #pragma unroll
  for (int h = 0; h < 2; h++){
    float fa[16][4];
    #pragma unroll
    for (int nb = 0; nb < 16; nb++){ fa[nb][0]=fa[nb][1]=fa[nb][2]=fa[nb][3]=0.f; }
    #pragma unroll
    for (int kb = 0; kb < 4; kb++){
      uint32_t brow = Ks_u + (uint32_t)(kb*16)*528 + h*256 + b_off1;
      #pragma unroll
      for (int n2 = 0; n2 < 8; n2++){
        uint32_t bb[4];
        ldsm_x4_t(bb, brow + n2*32);
        mma_bf16(fa[2*n2  ][0],fa[2*n2  ][1],fa[2*n2  ][2],fa[2*n2  ][3],
                 af1[kb][0],af1[kb][1],af1[kb][2],af1[kb][3], bb[0],bb[1]);
        mma_bf16(fa[2*n2+1][0],fa[2*n2+1][1],fa[2*n2+1][2],fa[2*n2+1][3],
                 af1[kb][0],af1[kb][1],af1[kb][2],af1[kb][3], bb[2],bb[3]);
      }
    }
    #pragma unroll
    for (int nb = 0; nb < 16; nb++){
      int col = h*128 + nb*8 + tq*2;
      float b0 = fc1b[col], b1 = fc1b[col+1];
      *(uint32_t*)(fbout + r0*256 + col) = pack2(fa[nb][0]+b0, fa[nb][1]+b1);
      *(uint32_t*)(fbout + r1*256 + col) = pack2(fa[nb][2]+b0, fa[nb][3]+b1);
    }
  }
}

// ---------------- fused dwconv3x3 + GELU + fc2 + residual ----------------
__global__ void __launch_bounds__(256, 2) fc2_fused(
    const bf16* __restrict__ f, const float* __restrict__ dw,
    const bf16* __restrict__ w2, const float* __restrict__ bias2,
    const float* __restrict__ x2, float* __restrict__ out)
{
  extern __shared__ bf16 smf[];
  bf16* Ws = smf;                 // 256 x 72
  bf16* Fs = smf + 256*72;        // 3 x 128 x 72
  bf16* Gs = Fs  + 3*128*72;      // 128 x 72
  int t = threadIdx.x, w = t>>5, lane = t&31;
  int by = blockIdx.x;
  int b = by >> 7, y = by & 127;
  size_t tokbase = (size_t)b*NTOK + (size_t)y*128;

  for (int i = t; i < 2048; i += 256){
    int row = i>>3, c8 = i&7;
    *(float4*)(Ws + row*72 + c8*8) = *(const float4*)(w2 + row*64 + c8*8);
  }

  float acc[8][4];
  #pragma unroll
  for (int nb = 0; nb < 8; nb++){ acc[nb][0]=acc[nb][1]=acc[nb][2]=acc[nb][3]=0.f; }
  uint32_t Ws_u = (uint32_t)__cvta_generic_to_shared(Ws);
  uint32_t Gs_u = (uint32_t)__cvta_generic_to_shared(Gs);
  uint32_t a_base = Gs_u + ((w*16 + (lane&15))*72 + (lane>>4)*8)*2;
  uint32_t b_off  = (lane&15)*144 + (lane>>4)*16;

  int chl = lane*2;
  int px0 = w*16;

  for (int kc = 0; kc < 256; kc += 64){
    __syncthreads();
    for (int i = t; i < 3072; i += 256){
      int row3 = i>>10, rem = i&1023, px = rem>>3, c8 = rem&7;
      int yy = y + row3 - 1;
      float4 val;
      if (yy >= 0 && yy < 128)
        val = *(const float4*)(f + ((size_t)b*NTOK + (size_t)yy*128 + px)*256 + kc + c8*8);
      else
        val = make_float4(0.f,0.f,0.f,0.f);
      *(float4*)(Fs + row3*9216 + px*72 + c8*8) = val;
    }
    __syncthreads();
    {
      float w9[2][9];
      #pragma unroll
      for (int i = 0; i < 9; i++){
        float2 wv = *(const float2*)(dw + i*256 + kc + chl);
        w9[0][i] = wv.x; w9[1][i] = wv.y;
      }
      float2 fv[3][3];
      #pragma unroll
      for (int dy = 0; dy < 3; dy++){
        uint32_t u0 = (px0 > 0) ? *(uint32_t*)(Fs + dy*9216 + (px0-1)*72 + chl) : 0u;
        uint32_t u1 = *(uint32_t*)(Fs + dy*9216 + px0*72 + chl);
        fv[0][dy] = __bfloat1622float2(*reinterpret_cast<const __nv_bfloat162*>(&u0));
        fv[1][dy] = __bfloat1622float2(*reinterpret_cast<const __nv_bfloat162*>(&u1));
      }
      #pragma unroll
      for (int pi = 0; pi < 16; pi++){
        int px = px0 + pi;
        #pragma unroll
        for (int dy = 0; dy < 3; dy++){
          uint32_t u = (px+1 < 128) ? *(uint32_t*)(Fs + dy*9216 + (px+1)*72 + chl) : 0u;
          fv[2][dy] = __bfloat1622float2(*reinterpret_cast<const __nv_bfloat162*>(&u));
        }
        float a0 = 0.f, a1 = 0.f;
        #pragma unroll
        for (int dy = 0; dy < 3; dy++)
          #pragma unroll
          for (int dx = 0; dx < 3; dx++){
            a0 = fmaf(fv[dx][dy].x, w9[0][dy*3+dx], a0);
            a1 = fmaf(fv[dx][dy].y, w9[1][dy*3+dx], a1);
          }
        a0 = 0.5f*a0*(1.0f + erff(a0*0.70710678118654752f));
        a1 = 0.5f*a1*(1.0f + erff(a1*0.70710678118654752f));
        *(uint32_t*)(Gs + px*72 + chl) = pack2(a0, a1);
        #pragma unroll
        for (int dy = 0; dy < 3; dy++){ fv[0][dy] = fv[1][dy]; fv[1][dy] = fv[2][dy]; }
      }
    }
    __syncwarp();
    #pragma unroll
    for (int kb = 0; kb < 4; kb++){
      uint32_t a[4];
      ldsm_x4(a, a_base + kb*32);
      uint32_t brow = Ws_u + (uint32_t)(kc + kb*16)*144 + b_off;
      #pragma unroll
      for (int n2 = 0; n2 < 4; n2++){
        uint32_t bb[4];
        ldsm_x4_t(bb, brow + n2*32);
        mma_bf16(acc[2*n2  ][0],acc[2*n2  ][1],acc[2*n2  ][2],acc[2*n2  ][3],
                 a[0],a[1],a[2],a[3], bb[0],bb[1]);
        mma_bf16(acc[2*n2+1][0],acc[2*n2+1][1],acc[2*n2+1][2],acc[2*n2+1][3],
                 a[0],a[1],a[2],a[3], bb[2],bb[3]);
      }
    }
  }

  int g = lane>>2, tq = lane&3;
  size_t r0 = tokbase + w*16 + g, r1 = r0 + 8;
  #pragma unroll
  for (int nb = 0; nb < 8; nb++){
    int col = nb*8 + tq*2;
    float b0 = bias2[col], b1 = bias2[col+1];
    float2 q0 = *(const float2*)(x2 + r0*64 + col);
    float2 q1 = *(const float2*)(x2 + r1*64 + col);
    *(float2*)(out + r0*64 + col) = make_float2(acc[nb][0]+b0+q0.x, acc[nb][1]+b1+q0.y);
    *(float2*)(out + r1*64 + col) = make_float2(acc[nb][2]+b0+q1.x, acc[nb][3]+b1+q1.y);
  }
}

// ---------------- launch ----------------
extern "C" void kernel_launch(void* const* d_in, const int* in_sizes, int n_in,
                              void* d_out, int out_size)
{
  const float* x      = (const float*)d_in[0];
  const float* ln1_g  = (const float*)d_in[3];
  const float* ln1_b  = (const float*)d_in[4];
  const float* q_w    = (const float*)d_in[5];
  const float* q_b    = (const float*)d_in[6];
  const float* kv_w   = (const float*)d_in[7];
  const float* kv_b   = (const float*)d_in[8];
  const float* proj_w = (const float*)d_in[9];
  const float* proj_b = (const float*)d_in[10];
  const float* sr_w   = (const float*)d_in[11];
  const float* sr_b   = (const float*)d_in[12];
  const float* srn_g  = (const float*)d_in[13];
  const float* srn_b  = (const float*)d_in[14];
  const float* ln2_g  = (const float*)d_in[15];
  const float* ln2_b  = (const float*)d_in[16];
  const float* fc1_w  = (const float*)d_in[17];
  const float* fc1_b  = (const float*)d_in[18];
  const float* dw_w   = (const float*)d_in[19];
  const float* fc2_w  = (const float*)d_in[20];
  const float* fc2_b  = (const float*)d_in[21];
  float* out = (float*)d_out;

  bf16 *hb,*fb,*kvbuf,*wq,*wkv,*wp,*wsr,*w1,*w2;
  float *x2;
  cudaGetSymbolAddress((void**)&hb,  g_hb);
  cudaGetSymbolAddress((void**)&x2,  g_x2);
  cudaGetSymbolAddress((void**)&fb,  g_fb);
  cudaGetSymbolAddress((void**)&kvbuf, g_kvb);
  cudaGetSymbolAddress((void**)&wq,  g_wq);
  cudaGetSymbolAddress((void**)&wkv, g_wkv);
  cudaGetSymbolAddress((void**)&wp,  g_wp);
  cudaGetSymbolAddress((void**)&wsr, g_wsr);
  cudaGetSymbolAddress((void**)&w1,  g_w1);
  cudaGetSymbolAddress((void**)&w2,  g_w2);

  const int SM_ATTN = (128 + 256 + 256 + 64)*72*2;    // 101376
  const int SM_FC2  = (256 + 3*128 + 128)*72*2;       // 110592

  cudaFuncSetAttribute((const void*)spatial_kv,
                       cudaFuncAttributeMaxDynamicSharedMemorySize, SKV_SMEM);
  cudaFuncSetAttribute((const void*)attn_fused,
                       cudaFuncAttributeMaxDynamicSharedMemorySize, SM_ATTN);
  cudaFuncSetAttribute((const void*)fc2_fused,
                       cudaFuncAttributeMaxDynamicSharedMemorySize, SM_FC2);

  CvtArgs ca = { q_w, kv_w, proj_w, sr_w, fc1_w, fc2_w, wq, wkv, wp, wsr, w1, w2 };
  cvt_all<<<1216, 256>>>(ca);
  ln1_kernel<<<1024, 256>>>(x, ln1_g, ln1_b, hb);
  spatial_kv<<<32, 256, SKV_SMEM>>>(hb, wsr, sr_b, srn_g, srn_b, wkv, kv_b, kvbuf);
  attn_fused<<<dim3(128, BB), 256, SM_ATTN>>>(hb, wq, q_b, kvbuf, wp, proj_b, x,
                                              ln2_g, ln2_b, w1, fc1_b, x2, fb);
  fc2_fused<<<1024, 256, SM_FC2>>>(fb, dw_w, w2, fc2_b, x2, out);
}